// round 1
// baseline (speedup 1.0000x reference)
#include <cuda_runtime.h>
#include <cuda_fp16.h>

#define NN 100000
#define EE 1600000
#define DD 128
#define HH 8
#define DHH 16

// ---------------- scratch (static device globals; no allocations) ----------------
__device__ float g_h[NN * DD];       // LN1 output
__device__ float g_feat0[NN * DD];   // h @ W^T
__device__ float g_fA[NN * DD];
__device__ float g_fB[NN * DD];
__device__ float g_eh[NN * HH];
__device__ float g_et[NN * HH];
__device__ int   g_count[NN];
__device__ int   g_cursor[NN];
__device__ int   g_rowptr[NN + 1];
__device__ int   g_srcs[EE];         // src index per CSR-sorted edge
__device__ float g_a[EE * HH];       // attention weights per sorted edge x head

// ---------------- utility kernels ----------------
__global__ void k_zero() {
    int i = blockIdx.x * 256 + threadIdx.x;
    if (i < NN) { g_count[i] = 0; g_cursor[i] = 0; }
}

__global__ void k_hist(const int* __restrict__ dst) {
    int e = blockIdx.x * 256 + threadIdx.x;
    if (e < EE) atomicAdd(&g_count[dst[e]], 1);
}

// single-block exclusive scan of g_count -> g_rowptr
__global__ void k_scan() {
    __shared__ int wsum[32];
    __shared__ int carry_total;
    int t = threadIdx.x, lane = t & 31, wid = t >> 5;
    if (t == 0) carry_total = 0;
    __syncthreads();
    for (int base = 0; base < NN; base += 4096) {
        int idx = base + t * 4;
        int v0 = (idx + 0 < NN) ? g_count[idx + 0] : 0;
        int v1 = (idx + 1 < NN) ? g_count[idx + 1] : 0;
        int v2 = (idx + 2 < NN) ? g_count[idx + 2] : 0;
        int v3 = (idx + 3 < NN) ? g_count[idx + 3] : 0;
        int s = v0 + v1 + v2 + v3;
        int x = s;
        #pragma unroll
        for (int d = 1; d < 32; d <<= 1) {
            int y = __shfl_up_sync(0xffffffffu, x, d);
            if (lane >= d) x += y;
        }
        if (lane == 31) wsum[wid] = x;
        __syncthreads();
        if (wid == 0) {
            int w = wsum[lane];
            #pragma unroll
            for (int d = 1; d < 32; d <<= 1) {
                int y = __shfl_up_sync(0xffffffffu, w, d);
                if (lane >= d) w += y;
            }
            wsum[lane] = w;
        }
        __syncthreads();
        int carry = carry_total;
        int wex = (wid == 0) ? 0 : wsum[wid - 1];
        int excl = carry + wex + (x - s);
        if (idx + 0 < NN) g_rowptr[idx + 0] = excl;
        if (idx + 1 < NN) g_rowptr[idx + 1] = excl + v0;
        if (idx + 2 < NN) g_rowptr[idx + 2] = excl + v0 + v1;
        if (idx + 3 < NN) g_rowptr[idx + 3] = excl + v0 + v1 + v2;
        __syncthreads();
        if (t == 0) carry_total += wsum[31];
        __syncthreads();
    }
    if (threadIdx.x == 0) g_rowptr[NN] = carry_total;
}

__global__ void k_scatter(const int* __restrict__ src, const int* __restrict__ dst) {
    int e = blockIdx.x * 256 + threadIdx.x;
    if (e < EE) {
        int d = dst[e];
        int pos = g_rowptr[d] + atomicAdd(&g_cursor[d], 1);
        g_srcs[pos] = src[e];
    }
}

// ---------------- k1: LN1 + h@W^T + attention dots ----------------
// dynamic shared: Wt[128*132] (transposed, padded) | ah[128] | at[128] | hs[8*128]
__global__ __launch_bounds__(256) void k1(const float* __restrict__ ent,
                                          const float* __restrict__ W,
                                          const float* __restrict__ ah,
                                          const float* __restrict__ at,
                                          const float* __restrict__ g1v,
                                          const float* __restrict__ b1v) {
    extern __shared__ float sm1[];
    float* Wt    = sm1;                     // [k*132 + j]
    float* sh_ah = sm1 + 128 * 132;
    float* sh_at = sh_ah + 128;
    float* hs    = sh_at + 128;             // [wid*128 + k]

    int tid = threadIdx.x, lane = tid & 31, wid = tid >> 5;
    for (int i = tid; i < 128 * 128; i += 256) {
        int j = i >> 7, k = i & 127;        // coalesced read W[j][k]
        Wt[k * 132 + j] = W[i];
    }
    for (int i = tid; i < 128; i += 256) { sh_ah[i] = ah[i]; sh_at[i] = at[i]; }
    __syncthreads();

    float4 g = ((const float4*)g1v)[lane];
    float4 b = ((const float4*)b1v)[lane];
    int hh = lane >> 2;
    int d0 = (lane & 3) * 4;
    float a0 = sh_ah[hh * 16 + d0 + 0], a1 = sh_ah[hh * 16 + d0 + 1];
    float a2 = sh_ah[hh * 16 + d0 + 2], a3 = sh_ah[hh * 16 + d0 + 3];
    float t0 = sh_at[hh * 16 + d0 + 0], t1 = sh_at[hh * 16 + d0 + 1];
    float t2 = sh_at[hh * 16 + d0 + 2], t3 = sh_at[hh * 16 + d0 + 3];

    int wg = blockIdx.x * 8 + wid;
    int stride = gridDim.x * 8;
    for (int r = wg; r < NN; r += stride) {
        float4 x = ((const float4*)ent)[r * 32 + lane];
        float s  = x.x + x.y + x.z + x.w;
        float sq = x.x * x.x + x.y * x.y + x.z * x.z + x.w * x.w;
        #pragma unroll
        for (int d = 16; d; d >>= 1) {
            s  += __shfl_xor_sync(0xffffffffu, s, d);
            sq += __shfl_xor_sync(0xffffffffu, sq, d);
        }
        float mean = s * 0.0078125f;
        float var  = sq * 0.0078125f - mean * mean;
        float rstd = rsqrtf(var + 1e-5f);
        float4 hv;
        hv.x = (x.x - mean) * rstd * g.x + b.x;
        hv.y = (x.y - mean) * rstd * g.y + b.y;
        hv.z = (x.z - mean) * rstd * g.z + b.z;
        hv.w = (x.w - mean) * rstd * g.w + b.w;
        ((float4*)g_h)[r * 32 + lane] = hv;
        *(float4*)&hs[wid * 128 + lane * 4] = hv;
        __syncwarp();

        float4 acc = make_float4(0.f, 0.f, 0.f, 0.f);
        #pragma unroll 2
        for (int k = 0; k < 128; k += 4) {
            float4 hk = *(const float4*)&hs[wid * 128 + k];
            float4 w0 = *(const float4*)&Wt[(k + 0) * 132 + lane * 4];
            acc.x += hk.x * w0.x; acc.y += hk.x * w0.y; acc.z += hk.x * w0.z; acc.w += hk.x * w0.w;
            float4 w1 = *(const float4*)&Wt[(k + 1) * 132 + lane * 4];
            acc.x += hk.y * w1.x; acc.y += hk.y * w1.y; acc.z += hk.y * w1.z; acc.w += hk.y * w1.w;
            float4 w2 = *(const float4*)&Wt[(k + 2) * 132 + lane * 4];
            acc.x += hk.z * w2.x; acc.y += hk.z * w2.y; acc.z += hk.z * w2.z; acc.w += hk.z * w2.w;
            float4 w3 = *(const float4*)&Wt[(k + 3) * 132 + lane * 4];
            acc.x += hk.w * w3.x; acc.y += hk.w * w3.y; acc.z += hk.w * w3.z; acc.w += hk.w * w3.w;
        }
        ((float4*)g_feat0)[r * 32 + lane] = acc;

        float pe = acc.x * a0 + acc.y * a1 + acc.z * a2 + acc.w * a3;
        float pt = acc.x * t0 + acc.y * t1 + acc.z * t2 + acc.w * t3;
        pe += __shfl_xor_sync(0xffffffffu, pe, 1);
        pe += __shfl_xor_sync(0xffffffffu, pe, 2);
        pt += __shfl_xor_sync(0xffffffffu, pt, 1);
        pt += __shfl_xor_sync(0xffffffffu, pt, 2);
        if ((lane & 3) == 0) {
            g_eh[r * 8 + hh] = pe;
            g_et[r * 8 + hh] = pt;
        }
        __syncwarp();
    }
}

// ---------------- segment softmax (warp per node) ----------------
__global__ __launch_bounds__(256) void k_softmax() {
    int v = blockIdx.x * 8 + (threadIdx.x >> 5);
    int lane = threadIdx.x & 31;
    if (v >= NN) return;
    int beg = g_rowptr[v], end = g_rowptr[v + 1];
    int head = lane & 7, eo = lane >> 3;
    float etv = g_et[v * 8 + head];
    float m = -1e30f;
    for (int e = beg + eo; e < end; e += 4) {
        int s = __ldg(&g_srcs[e]);
        float sc = __ldg(&g_eh[s * 8 + head]) + etv;
        sc = sc > 0.f ? sc : 0.2f * sc;
        m = fmaxf(m, sc);
    }
    m = fmaxf(m, __shfl_xor_sync(0xffffffffu, m, 8));
    m = fmaxf(m, __shfl_xor_sync(0xffffffffu, m, 16));
    float ssum = 0.f;
    for (int e = beg + eo; e < end; e += 4) {
        int s = __ldg(&g_srcs[e]);
        float sc = __ldg(&g_eh[s * 8 + head]) + etv;
        sc = sc > 0.f ? sc : 0.2f * sc;
        float av = __expf(sc - m);
        g_a[e * 8 + head] = av;
        ssum += av;
    }
    ssum += __shfl_xor_sync(0xffffffffu, ssum, 8);
    ssum += __shfl_xor_sync(0xffffffffu, ssum, 16);
    float inv = 1.f / ssum;
    for (int e = beg + eo; e < end; e += 4) {
        g_a[e * 8 + head] *= inv;
    }
}

// ---------------- propagation hop (warp per node) ----------------
__global__ __launch_bounds__(256) void k_hop(int which) {
    const float* fin  = (which == 0) ? g_feat0 : ((which & 1) ? g_fA : g_fB);
    float*       fout = (which & 1) ? g_fB : g_fA;
    int v = blockIdx.x * 8 + (threadIdx.x >> 5);
    int lane = threadIdx.x & 31;
    if (v >= NN) return;
    int beg = g_rowptr[v], end = g_rowptr[v + 1];
    int hh = lane >> 2;
    float4 acc = make_float4(0.f, 0.f, 0.f, 0.f);
    const float4* f4 = (const float4*)fin;
    for (int e = beg; e < end; e++) {
        int s    = __ldg(&g_srcs[e]);
        float av = __ldg(&g_a[e * 8 + hh]);
        float4 fv = __ldg(&f4[s * 32 + lane]);
        acc.x += av * fv.x; acc.y += av * fv.y; acc.z += av * fv.z; acc.w += av * fv.w;
    }
    float4 f0 = __ldg(&((const float4*)g_feat0)[v * 32 + lane]);
    float4 o;
    o.x = 0.85f * acc.x + 0.15f * f0.x;
    o.y = 0.85f * acc.y + 0.15f * f0.y;
    o.z = 0.85f * acc.z + 0.15f * f0.z;
    o.w = 0.85f * acc.w + 0.15f * f0.w;
    ((float4*)fout)[v * 32 + lane] = o;
}

// ---------------- FFN: rst = fB + h; LN2; relu(x@w1^T+b1)@w2^T+b2 + rst ----------------
__device__ __forceinline__ void mma_m16n8k16(float* c, const unsigned* a, const unsigned* b) {
    asm volatile(
        "mma.sync.aligned.m16n8k16.row.col.f32.f16.f16.f32 "
        "{%0,%1,%2,%3}, {%4,%5,%6,%7}, {%8,%9}, {%0,%1,%2,%3};\n"
        : "+f"(c[0]), "+f"(c[1]), "+f"(c[2]), "+f"(c[3])
        : "r"(a[0]), "r"(a[1]), "r"(a[2]), "r"(a[3]), "r"(b[0]), "r"(b[1]));
}

#define XS_OFF   0
#define W1S_OFF  (34816)
#define RS_OFF   (34816 + 17408)
#define W2S_OFF  (34816 + 17408 + 18432)
#define RST_OFF  (34816 + 17408 + 18432 + 18432)
#define FFN_SMEM (34816 + 17408 + 18432 + 18432 + 67584)

__global__ __launch_bounds__(256) void k_ffn(float* __restrict__ out,
                                             const float* __restrict__ g2,
                                             const float* __restrict__ b2v,
                                             const float* __restrict__ w1g,
                                             const float* __restrict__ b1g,
                                             const float* __restrict__ w2g,
                                             const float* __restrict__ b2g) {
    extern __shared__ char smem[];
    __half* Xs   = (__half*)(smem + XS_OFF);    // [128][136]
    __half* w1s  = (__half*)(smem + W1S_OFF);   // [64][136]
    __half* Rs   = (__half*)(smem + RS_OFF);    // [128][72]
    __half* w2s  = (__half*)(smem + W2S_OFF);   // [128][72]
    float*  rsts = (float*)(smem + RST_OFF);    // [128][132]

    int tid = threadIdx.x, lane = tid & 31, wid = tid >> 5;
    int g = lane >> 2, t = lane & 3;
    int rows_base = blockIdx.x * 128;

    float4 gg = ((const float4*)g2)[lane];
    float4 bb = ((const float4*)b2v)[lane];

    // prologue: rst + LN2 + fp16 X (each warp owns 16 rows)
    for (int i = 0; i < 16; i++) {
        int rl = wid * 16 + i;
        int r = rows_base + rl;
        if (r >= NN) r = NN - 1;
        float4 fv = __ldg(&((const float4*)g_fB)[r * 32 + lane]);
        float4 hv = __ldg(&((const float4*)g_h)[r * 32 + lane]);
        float4 rv;
        rv.x = fv.x + hv.x; rv.y = fv.y + hv.y; rv.z = fv.z + hv.z; rv.w = fv.w + hv.w;
        *(float4*)&rsts[rl * 132 + lane * 4] = rv;
        float s  = rv.x + rv.y + rv.z + rv.w;
        float sq = rv.x * rv.x + rv.y * rv.y + rv.z * rv.z + rv.w * rv.w;
        #pragma unroll
        for (int d = 16; d; d >>= 1) {
            s  += __shfl_xor_sync(0xffffffffu, s, d);
            sq += __shfl_xor_sync(0xffffffffu, sq, d);
        }
        float mean = s * 0.0078125f;
        float var  = sq * 0.0078125f - mean * mean;
        float rstd = rsqrtf(var + 1e-5f);
        float4 xv;
        xv.x = (rv.x - mean) * rstd * gg.x + bb.x;
        xv.y = (rv.y - mean) * rstd * gg.y + bb.y;
        xv.z = (rv.z - mean) * rstd * gg.z + bb.z;
        xv.w = (rv.w - mean) * rstd * gg.w + bb.w;
        __half2* xp = (__half2*)&Xs[rl * 136 + lane * 4];
        xp[0] = __floats2half2_rn(xv.x, xv.y);
        xp[1] = __floats2half2_rn(xv.z, xv.w);
    }

    float fc[2][8][4];
    #pragma unroll
    for (int i2 = 0; i2 < 2; i2++)
        #pragma unroll
        for (int j = 0; j < 8; j++)
            #pragma unroll
            for (int c = 0; c < 4; c++) fc[i2][j][c] = 0.f;

    int wm = wid >> 1, wn = wid & 1;
    int ma = wm * 32, nb = wn * 64;

    for (int jc = 0; jc < 8; jc++) {
        __syncthreads();
        // load current w1/w2 chunks (fp32 -> fp16)
        for (int i = tid; i < 64 * 128; i += 256) {
            int rr = i >> 7, cc = i & 127;
            w1s[rr * 136 + cc] = __float2half_rn(__ldg(&w1g[(jc * 64 + rr) * 128 + cc]));
        }
        for (int i = tid; i < 128 * 64; i += 256) {
            int rr = i >> 6, cc = i & 63;
            w2s[rr * 72 + cc] = __float2half_rn(__ldg(&w2g[rr * 512 + jc * 64 + cc]));
        }
        __syncthreads();

        // GEMM1: warp computes rows [wid*16, +16) x 64 chunk cols
        float y[8][4];
        #pragma unroll
        for (int j = 0; j < 8; j++)
            #pragma unroll
            for (int c = 0; c < 4; c++) y[j][c] = 0.f;
        int m0 = wid * 16;
        #pragma unroll
        for (int k0 = 0; k0 < 128; k0 += 16) {
            unsigned a[4];
            a[0] = *(const unsigned*)&Xs[(m0 + g) * 136 + k0 + t * 2];
            a[1] = *(const unsigned*)&Xs[(m0 + g + 8) * 136 + k0 + t * 2];
            a[2] = *(const unsigned*)&Xs[(m0 + g) * 136 + k0 + t * 2 + 8];
            a[3] = *(const unsigned*)&Xs[(m0 + g + 8) * 136 + k0 + t * 2 + 8];
            #pragma unroll
            for (int j = 0; j < 8; j++) {
                unsigned bf[2];
                bf[0] = *(const unsigned*)&w1s[(j * 8 + g) * 136 + k0 + t * 2];
                bf[1] = *(const unsigned*)&w1s[(j * 8 + g) * 136 + k0 + t * 2 + 8];
                mma_m16n8k16(y[j], a, bf);
            }
        }
        // bias + relu -> Rs (fp16)
        #pragma unroll
        for (int j = 0; j < 8; j++) {
            int colg = jc * 64 + j * 8 + t * 2;
            float bb0 = __ldg(&b1g[colg]);
            float bb1 = __ldg(&b1g[colg + 1]);
            float v0 = fmaxf(y[j][0] + bb0, 0.f);
            float v1 = fmaxf(y[j][1] + bb1, 0.f);
            float v2 = fmaxf(y[j][2] + bb0, 0.f);
            float v3 = fmaxf(y[j][3] + bb1, 0.f);
            *(__half2*)&Rs[(m0 + g) * 72 + j * 8 + t * 2]     = __floats2half2_rn(v0, v1);
            *(__half2*)&Rs[(m0 + g + 8) * 72 + j * 8 + t * 2] = __floats2half2_rn(v2, v3);
        }
        __syncthreads();

        // GEMM2 accumulate: warp tile 32 rows x 64 cols
        #pragma unroll
        for (int k0 = 0; k0 < 64; k0 += 16) {
            unsigned aA[4], aB[4];
            aA[0] = *(const unsigned*)&Rs[(ma + g) * 72 + k0 + t * 2];
            aA[1] = *(const unsigned*)&Rs[(ma + g + 8) * 72 + k0 + t * 2];
            aA[2] = *(const unsigned*)&Rs[(ma + g) * 72 + k0 + t * 2 + 8];
            aA[3] = *(const unsigned*)&Rs[(ma + g + 8) * 72 + k0 + t * 2 + 8];
            aB[0] = *(const unsigned*)&Rs[(ma + 16 + g) * 72 + k0 + t * 2];
            aB[1] = *(const unsigned*)&Rs[(ma + 24 + g) * 72 + k0 + t * 2];
            aB[2] = *(const unsigned*)&Rs[(ma + 16 + g) * 72 + k0 + t * 2 + 8];
            aB[3] = *(const unsigned*)&Rs[(ma + 24 + g) * 72 + k0 + t * 2 + 8];
            #pragma unroll
            for (int j = 0; j < 8; j++) {
                unsigned bf[2];
                bf[0] = *(const unsigned*)&w2s[(nb + j * 8 + g) * 72 + k0 + t * 2];
                bf[1] = *(const unsigned*)&w2s[(nb + j * 8 + g) * 72 + k0 + t * 2 + 8];
                mma_m16n8k16(fc[0][j], aA, bf);
                mma_m16n8k16(fc[1][j], aB, bf);
            }
        }
    }

    // epilogue: out = fc + b2 + rst
    #pragma unroll
    for (int i2 = 0; i2 < 2; i2++) {
        #pragma unroll
        for (int j = 0; j < 8; j++) {
            int rl  = ma + i2 * 16 + g;
            int col = nb + j * 8 + t * 2;
            float b20 = __ldg(&b2g[col]);
            float b21 = __ldg(&b2g[col + 1]);
            int r0 = rows_base + rl;
            if (r0 < NN) {
                float2 o;
                o.x = fc[i2][j][0] + b20 + rsts[rl * 132 + col];
                o.y = fc[i2][j][1] + b21 + rsts[rl * 132 + col + 1];
                *(float2*)&out[r0 * 128 + col] = o;
            }
            int r8 = r0 + 8;
            if (r8 < NN) {
                float2 o;
                o.x = fc[i2][j][2] + b20 + rsts[(rl + 8) * 132 + col];
                o.y = fc[i2][j][3] + b21 + rsts[(rl + 8) * 132 + col + 1];
                *(float2*)&out[r8 * 128 + col] = o;
            }
        }
    }
}

#define K1_SMEM ((128 * 132 + 128 + 128 + 8 * 128) * 4)

extern "C" void kernel_launch(void* const* d_in, const int* in_sizes, int n_in,
                              void* d_out, int out_size) {
    const float* ent    = (const float*)d_in[0];
    const int*   src    = (const int*)d_in[1];
    const int*   dst    = (const int*)d_in[2];
    const float* W_ent  = (const float*)d_in[3];
    const float* attn_h = (const float*)d_in[4];
    const float* attn_t = (const float*)d_in[5];
    const float* ln1_g  = (const float*)d_in[6];
    const float* ln1_b  = (const float*)d_in[7];
    const float* ln2_g  = (const float*)d_in[8];
    const float* ln2_b  = (const float*)d_in[9];
    const float* w1     = (const float*)d_in[10];
    const float* b1     = (const float*)d_in[11];
    const float* w2     = (const float*)d_in[12];
    const float* b2     = (const float*)d_in[13];
    float* out = (float*)d_out;

    cudaFuncSetAttribute(k_ffn, cudaFuncAttributeMaxDynamicSharedMemorySize, FFN_SMEM);
    cudaFuncSetAttribute(k1, cudaFuncAttributeMaxDynamicSharedMemorySize, K1_SMEM);

    k_zero<<<(NN + 255) / 256, 256>>>();
    k1<<<444, 256, K1_SMEM>>>(ent, W_ent, attn_h, attn_t, ln1_g, ln1_b);
    k_hist<<<EE / 256, 256>>>(dst);
    k_scan<<<1, 1024>>>();
    k_scatter<<<EE / 256, 256>>>(src, dst);
    k_softmax<<<NN / 8, 256>>>();
    for (int hop = 0; hop < 6; hop++) {
        k_hop<<<NN / 8, 256>>>(hop);
    }
    k_ffn<<<(NN + 127) / 128, 256, FFN_SMEM>>>(out, ln2_g, ln2_b, w1, b1, w2, b2);
}

// round 4
// speedup vs baseline: 1.2805x; 1.2805x over previous
#include <cuda_runtime.h>
#include <cuda_fp16.h>

#define NN 100000
#define EE 1600000
#define DD 128
#define HH 8

// ---------------- scratch (static device globals; no allocations) ----------------
__device__ float  g_h[NN * DD];        // LN1 output (fp32, needed for rst)
__device__ float  g_feat0[NN * DD];    // h @ W^T (fp32 anchor for ALPHA term)
__device__ __half g_f0h[NN * DD];      // fp16 copy of feat0 (hop-0 gather input)
__device__ __half g_hA[NN * DD];       // ping
__device__ __half g_hB[NN * DD];       // pong (final hop output)
__device__ float  g_eh[NN * HH];
__device__ float  g_et[NN * HH];
__device__ int    g_count[NN];
__device__ int    g_cursor[NN];
__device__ int    g_rowptr[NN + 1];
__device__ int    g_srcs[EE];          // src per CSR-sorted edge
__device__ __half g_ah[EE * HH];       // normalized attention (fp16)
__device__ int    g_bsum[512];
__device__ int    g_boff[512];

#define SCAN_NB 391  // ceil(NN/256)

// ---------------- CSR build ----------------
__global__ void k_zero() {
    int i = blockIdx.x * 256 + threadIdx.x;
    if (i < NN) { g_count[i] = 0; g_cursor[i] = 0; }
}

__global__ void k_hist(const int* __restrict__ dst) {
    int e = blockIdx.x * 256 + threadIdx.x;
    if (e < EE) atomicAdd(&g_count[dst[e]], 1);
}

// pass 1: per-block inclusive scan -> rowptr[i+1], block totals -> g_bsum
__global__ __launch_bounds__(256) void k_scan1() {
    __shared__ int ws[8];
    int t = threadIdx.x, lane = t & 31, wid = t >> 5;
    int i = blockIdx.x * 256 + t;
    int v = (i < NN) ? g_count[i] : 0;
    int x = v;
    #pragma unroll
    for (int d = 1; d < 32; d <<= 1) {
        int y = __shfl_up_sync(0xffffffffu, x, d);
        if (lane >= d) x += y;
    }
    if (lane == 31) ws[wid] = x;
    __syncthreads();
    if (wid == 0) {
        int w = (lane < 8) ? ws[lane] : 0;
        #pragma unroll
        for (int d = 1; d < 8; d <<= 1) {
            int y = __shfl_up_sync(0xffffffffu, w, d);
            if (lane >= d) w += y;
        }
        if (lane < 8) ws[lane] = w;
    }
    __syncthreads();
    x += (wid ? ws[wid - 1] : 0);
    if (i < NN) g_rowptr[i + 1] = x;
    if (t == 255) g_bsum[blockIdx.x] = x;
}

// pass 2: exclusive scan of 391 block totals (single block, 512 threads)
__global__ __launch_bounds__(512) void k_scan2() {
    __shared__ int ws[16];
    int t = threadIdx.x, lane = t & 31, wid = t >> 5;
    int v = (t < SCAN_NB) ? g_bsum[t] : 0;
    int x = v;
    #pragma unroll
    for (int d = 1; d < 32; d <<= 1) {
        int y = __shfl_up_sync(0xffffffffu, x, d);
        if (lane >= d) x += y;
    }
    if (lane == 31) ws[wid] = x;
    __syncthreads();
    if (wid == 0) {
        int w = (lane < 16) ? ws[lane] : 0;
        #pragma unroll
        for (int d = 1; d < 16; d <<= 1) {
            int y = __shfl_up_sync(0xffffffffu, w, d);
            if (lane >= d) w += y;
        }
        if (lane < 16) ws[lane] = w;
    }
    __syncthreads();
    x += (wid ? ws[wid - 1] : 0);
    if (t < SCAN_NB) g_boff[t] = x - v;
}

// pass 3: add block offsets
__global__ void k_scan3() {
    int i = blockIdx.x * 256 + threadIdx.x;
    if (i < NN) g_rowptr[i + 1] += g_boff[i >> 8];
    if (i == 0) g_rowptr[0] = 0;
}

__global__ void k_scatter(const int* __restrict__ src, const int* __restrict__ dst) {
    int e = blockIdx.x * 256 + threadIdx.x;
    if (e < EE) {
        int d = dst[e];
        int pos = g_rowptr[d] + atomicAdd(&g_cursor[d], 1);
        g_srcs[pos] = src[e];
    }
}

// ---------------- mma helper ----------------
__device__ __forceinline__ void mma_m16n8k16(float* c, const unsigned* a, const unsigned* b) {
    asm volatile(
        "mma.sync.aligned.m16n8k16.row.col.f32.f16.f16.f32 "
        "{%0,%1,%2,%3}, {%4,%5,%6,%7}, {%8,%9}, {%0,%1,%2,%3};\n"
        : "+f"(c[0]), "+f"(c[1]), "+f"(c[2]), "+f"(c[3])
        : "r"(a[0]), "r"(a[1]), "r"(a[2]), "r"(a[3]), "r"(b[0]), "r"(b[1]));
}

// ---------------- k1: LN1 + h@W^T (tensor core) + attention dots ----------------
// smem layout: sh_ah[128]f | sh_at[128]f | (Ws[128][136]h | Xs[128][136]h)  U  fs[128][132]f
#define K1_AH   0
#define K1_AT   512
#define K1_WS   1024
#define K1_XS   (1024 + 34816)
#define K1_FS   1024
#define K1_SMEM (1024 + 34816 + 34816)

__global__ __launch_bounds__(256) void k1(const float* __restrict__ ent,
                                          const float* __restrict__ W,
                                          const float* __restrict__ ah,
                                          const float* __restrict__ at,
                                          const float* __restrict__ g1v,
                                          const float* __restrict__ b1v) {
    extern __shared__ char sm[];
    float*  sh_ah = (float*)(sm + K1_AH);
    float*  sh_at = (float*)(sm + K1_AT);
    __half* Ws    = (__half*)(sm + K1_WS);
    __half* Xs    = (__half*)(sm + K1_XS);
    float*  fs    = (float*)(sm + K1_FS);

    int tid = threadIdx.x, lane = tid & 31, wid = tid >> 5;
    int g = lane >> 2, t = lane & 3;
    int rows_base = blockIdx.x * 128;

    for (int i = tid; i < 128 * 128; i += 256) {
        Ws[(i >> 7) * 136 + (i & 127)] = __float2half_rn(W[i]);
    }
    for (int i = tid; i < 128; i += 256) { sh_ah[i] = ah[i]; sh_at[i] = at[i]; }

    float4 gg = ((const float4*)g1v)[lane];
    float4 bb = ((const float4*)b1v)[lane];

    // LN1 prologue: warp owns 16 rows
    for (int i = 0; i < 16; i++) {
        int rl = wid * 16 + i;
        int r = rows_base + rl;
        int rc = (r < NN) ? r : (NN - 1);
        float4 x = __ldg(&((const float4*)ent)[rc * 32 + lane]);
        float s  = x.x + x.y + x.z + x.w;
        float sq = x.x * x.x + x.y * x.y + x.z * x.z + x.w * x.w;
        #pragma unroll
        for (int d = 16; d; d >>= 1) {
            s  += __shfl_xor_sync(0xffffffffu, s, d);
            sq += __shfl_xor_sync(0xffffffffu, sq, d);
        }
        float mean = s * 0.0078125f;
        float var  = sq * 0.0078125f - mean * mean;
        float rstd = rsqrtf(var + 1e-5f);
        float4 hv;
        hv.x = (x.x - mean) * rstd * gg.x + bb.x;
        hv.y = (x.y - mean) * rstd * gg.y + bb.y;
        hv.z = (x.z - mean) * rstd * gg.z + bb.z;
        hv.w = (x.w - mean) * rstd * gg.w + bb.w;
        if (r < NN) ((float4*)g_h)[r * 32 + lane] = hv;
        __half2* xp = (__half2*)&Xs[rl * 136 + lane * 4];
        xp[0] = __floats2half2_rn(hv.x, hv.y);
        xp[1] = __floats2half2_rn(hv.z, hv.w);
    }
    __syncthreads();

    // GEMM: warp computes rows [wid*16, +16) x all 128 cols
    float y[16][4];
    #pragma unroll
    for (int j = 0; j < 16; j++)
        #pragma unroll
        for (int c = 0; c < 4; c++) y[j][c] = 0.f;
    int m0 = wid * 16;
    #pragma unroll
    for (int k0 = 0; k0 < 128; k0 += 16) {
        unsigned a[4];
        a[0] = *(const unsigned*)&Xs[(m0 + g) * 136 + k0 + t * 2];
        a[1] = *(const unsigned*)&Xs[(m0 + g + 8) * 136 + k0 + t * 2];
        a[2] = *(const unsigned*)&Xs[(m0 + g) * 136 + k0 + t * 2 + 8];
        a[3] = *(const unsigned*)&Xs[(m0 + g + 8) * 136 + k0 + t * 2 + 8];
        #pragma unroll
        for (int j = 0; j < 16; j++) {
            unsigned bf[2];
            bf[0] = *(const unsigned*)&Ws[(j * 8 + g) * 136 + k0 + t * 2];
            bf[1] = *(const unsigned*)&Ws[(j * 8 + g) * 136 + k0 + t * 2 + 8];
            mma_m16n8k16(y[j], a, bf);
        }
    }
    __syncthreads();   // Ws/Xs dead; fs aliases them

    // store feat (fp32 + fp16 global) and fs (smem for dots)
    #pragma unroll
    for (int j = 0; j < 16; j++) {
        int col = j * 8 + t * 2;
        int rl0 = m0 + g;
        fs[rl0 * 132 + col]       = y[j][0];
        fs[rl0 * 132 + col + 1]   = y[j][1];
        fs[(rl0 + 8) * 132 + col]     = y[j][2];
        fs[(rl0 + 8) * 132 + col + 1] = y[j][3];
        int r0 = rows_base + rl0;
        if (r0 < NN) {
            *(float2*)&g_feat0[(size_t)r0 * 128 + col] = make_float2(y[j][0], y[j][1]);
            *(__half2*)&g_f0h[(size_t)r0 * 128 + col]  = __floats2half2_rn(y[j][0], y[j][1]);
        }
        if (r0 + 8 < NN) {
            *(float2*)&g_feat0[(size_t)(r0 + 8) * 128 + col] = make_float2(y[j][2], y[j][3]);
            *(__half2*)&g_f0h[(size_t)(r0 + 8) * 128 + col]  = __floats2half2_rn(y[j][2], y[j][3]);
        }
    }
    __syncthreads();

    // attention dots: lane covers 4 consecutive dims of head hh2
    int hh2 = lane >> 2;
    int d0 = (lane & 3) * 4;
    float a0 = sh_ah[hh2 * 16 + d0 + 0], a1 = sh_ah[hh2 * 16 + d0 + 1];
    float a2 = sh_ah[hh2 * 16 + d0 + 2], a3 = sh_ah[hh2 * 16 + d0 + 3];
    float t0 = sh_at[hh2 * 16 + d0 + 0], t1 = sh_at[hh2 * 16 + d0 + 1];
    float t2 = sh_at[hh2 * 16 + d0 + 2], t3 = sh_at[hh2 * 16 + d0 + 3];
    for (int i = 0; i < 16; i++) {
        int rl = wid * 16 + i;
        int r = rows_base + rl;
        float4 f = *(const float4*)&fs[rl * 132 + lane * 4];
        float pe = f.x * a0 + f.y * a1 + f.z * a2 + f.w * a3;
        float pt = f.x * t0 + f.y * t1 + f.z * t2 + f.w * t3;
        pe += __shfl_xor_sync(0xffffffffu, pe, 1);
        pe += __shfl_xor_sync(0xffffffffu, pe, 2);
        pt += __shfl_xor_sync(0xffffffffu, pt, 1);
        pt += __shfl_xor_sync(0xffffffffu, pt, 2);
        if ((lane & 3) == 0 && r < NN) {
            g_eh[r * 8 + hh2] = pe;
            g_et[r * 8 + hh2] = pt;
        }
    }
}

// ---------------- segment softmax: 3 passes, exp recompute, fp16 store ----------------
__global__ __launch_bounds__(256) void k_softmax() {
    int v = blockIdx.x * 8 + (threadIdx.x >> 5);
    int lane = threadIdx.x & 31;
    if (v >= NN) return;
    int beg = g_rowptr[v], end = g_rowptr[v + 1];
    int head = lane & 7, eo = lane >> 3;
    float etv = g_et[v * 8 + head];

    float m = -1e30f;
    for (int e = beg + eo; e < end; e += 4) {
        int s = __ldg(&g_srcs[e]);
        float sc = __ldg(&g_eh[s * 8 + head]) + etv;
        sc = sc > 0.f ? sc : 0.2f * sc;
        m = fmaxf(m, sc);
    }
    m = fmaxf(m, __shfl_xor_sync(0xffffffffu, m, 8));
    m = fmaxf(m, __shfl_xor_sync(0xffffffffu, m, 16));

    float ssum = 0.f;
    for (int e = beg + eo; e < end; e += 4) {
        int s = __ldg(&g_srcs[e]);
        float sc = __ldg(&g_eh[s * 8 + head]) + etv;
        sc = sc > 0.f ? sc : 0.2f * sc;
        ssum += __expf(sc - m);
    }
    ssum += __shfl_xor_sync(0xffffffffu, ssum, 8);
    ssum += __shfl_xor_sync(0xffffffffu, ssum, 16);
    float inv = 1.f / ssum;

    for (int e = beg + eo; e < end; e += 4) {
        int s = __ldg(&g_srcs[e]);
        float sc = __ldg(&g_eh[s * 8 + head]) + etv;
        sc = sc > 0.f ? sc : 0.2f * sc;
        g_ah[e * 8 + head] = __float2half_rn(__expf(sc - m) * inv);
    }
}

// ---------------- propagation hop (warp per node, fp16 gather, fp32 accumulate) ----------------
__global__ __launch_bounds__(256) void k_hop(int which) {
    const __half* fin  = (which == 0) ? g_f0h : ((which & 1) ? g_hA : g_hB);
    __half*       fout = (which & 1) ? g_hB : g_hA;
    int v = blockIdx.x * 8 + (threadIdx.x >> 5);
    int lane = threadIdx.x & 31;
    if (v >= NN) return;
    int beg = g_rowptr[v], end = g_rowptr[v + 1];
    int hh = lane >> 2;
    float4 acc = make_float4(0.f, 0.f, 0.f, 0.f);
    for (int e = beg; e < end; e++) {
        int s = __ldg(&g_srcs[e]);
        float av = __half2float(__ldg(&g_ah[e * 8 + hh]));
        uint2 p = __ldg(((const uint2*)(fin + (size_t)s * 128)) + lane);
        __half2 h0 = *(__half2*)&p.x;
        __half2 h1 = *(__half2*)&p.y;
        float2 f0 = __half22float2(h0);
        float2 f1 = __half22float2(h1);
        acc.x += av * f0.x; acc.y += av * f0.y;
        acc.z += av * f1.x; acc.w += av * f1.y;
    }
    float4 f0v = __ldg(&((const float4*)g_feat0)[(size_t)v * 32 + lane]);
    float ox = 0.85f * acc.x + 0.15f * f0v.x;
    float oy = 0.85f * acc.y + 0.15f * f0v.y;
    float oz = 0.85f * acc.z + 0.15f * f0v.z;
    float ow = 0.85f * acc.w + 0.15f * f0v.w;
    __half2 o0 = __floats2half2_rn(ox, oy);
    __half2 o1 = __floats2half2_rn(oz, ow);
    uint2 val;
    val.x = *(unsigned*)&o0;
    val.y = *(unsigned*)&o1;
    ((uint2*)(fout + (size_t)v * 128))[lane] = val;
}

// ---------------- FFN: rst = hB + h; LN2; relu(x@w1^T+b1)@w2^T+b2 + rst ----------------
#define XS_OFF   0
#define W1S_OFF  (34816)
#define RS_OFF   (34816 + 17408)
#define W2S_OFF  (34816 + 17408 + 18432)
#define RST_OFF  (34816 + 17408 + 18432 + 18432)
#define FFN_SMEM (34816 + 17408 + 18432 + 18432 + 67584)

__global__ __launch_bounds__(256) void k_ffn(float* __restrict__ out,
                                             const float* __restrict__ g2,
                                             const float* __restrict__ b2v,
                                             const float* __restrict__ w1g,
                                             const float* __restrict__ b1g,
                                             const float* __restrict__ w2g,
                                             const float* __restrict__ b2g) {
    extern __shared__ char smem[];
    __half* Xs   = (__half*)(smem + XS_OFF);    // [128][136]
    __half* w1s  = (__half*)(smem + W1S_OFF);   // [64][136]
    __half* Rs   = (__half*)(smem + RS_OFF);    // [128][72]
    __half* w2s  = (__half*)(smem + W2S_OFF);   // [128][72]
    float*  rsts = (float*)(smem + RST_OFF);    // [128][132]

    int tid = threadIdx.x, lane = tid & 31, wid = tid >> 5;
    int g = lane >> 2, t = lane & 3;
    int rows_base = blockIdx.x * 128;

    float4 gg = ((const float4*)g2)[lane];
    float4 bb = ((const float4*)b2v)[lane];

    // prologue: rst + LN2 + fp16 X
    for (int i = 0; i < 16; i++) {
        int rl = wid * 16 + i;
        int r = rows_base + rl;
        if (r >= NN) r = NN - 1;
        uint2 p = __ldg(((const uint2*)(g_hB + (size_t)r * 128)) + lane);
        __half2 h0 = *(__half2*)&p.x;
        __half2 h1 = *(__half2*)&p.y;
        float2 f0 = __half22float2(h0);
        float2 f1 = __half22float2(h1);
        float4 hv = __ldg(&((const float4*)g_h)[(size_t)r * 32 + lane]);
        float4 rv;
        rv.x = f0.x + hv.x; rv.y = f0.y + hv.y; rv.z = f1.x + hv.z; rv.w = f1.y + hv.w;
        *(float4*)&rsts[rl * 132 + lane * 4] = rv;
        float s  = rv.x + rv.y + rv.z + rv.w;
        float sq = rv.x * rv.x + rv.y * rv.y + rv.z * rv.z + rv.w * rv.w;
        #pragma unroll
        for (int d = 16; d; d >>= 1) {
            s  += __shfl_xor_sync(0xffffffffu, s, d);
            sq += __shfl_xor_sync(0xffffffffu, sq, d);
        }
        float mean = s * 0.0078125f;
        float var  = sq * 0.0078125f - mean * mean;
        float rstd = rsqrtf(var + 1e-5f);
        float4 xv;
        xv.x = (rv.x - mean) * rstd * gg.x + bb.x;
        xv.y = (rv.y - mean) * rstd * gg.y + bb.y;
        xv.z = (rv.z - mean) * rstd * gg.z + bb.z;
        xv.w = (rv.w - mean) * rstd * gg.w + bb.w;
        __half2* xp = (__half2*)&Xs[rl * 136 + lane * 4];
        xp[0] = __floats2half2_rn(xv.x, xv.y);
        xp[1] = __floats2half2_rn(xv.z, xv.w);
    }

    float fc[2][8][4];
    #pragma unroll
    for (int i2 = 0; i2 < 2; i2++)
        #pragma unroll
        for (int j = 0; j < 8; j++)
            #pragma unroll
            for (int c = 0; c < 4; c++) fc[i2][j][c] = 0.f;

    int wm = wid >> 1, wn = wid & 1;
    int ma = wm * 32, nb = wn * 64;

    for (int jc = 0; jc < 8; jc++) {
        __syncthreads();
        for (int i = tid; i < 64 * 128; i += 256) {
            int rr = i >> 7, cc = i & 127;
            w1s[rr * 136 + cc] = __float2half_rn(__ldg(&w1g[(jc * 64 + rr) * 128 + cc]));
        }
        for (int i = tid; i < 128 * 64; i += 256) {
            int rr = i >> 6, cc = i & 63;
            w2s[rr * 72 + cc] = __float2half_rn(__ldg(&w2g[rr * 512 + jc * 64 + cc]));
        }
        __syncthreads();

        float y[8][4];
        #pragma unroll
        for (int j = 0; j < 8; j++)
            #pragma unroll
            for (int c = 0; c < 4; c++) y[j][c] = 0.f;
        int m0 = wid * 16;
        #pragma unroll
        for (int k0 = 0; k0 < 128; k0 += 16) {
            unsigned a[4];
            a[0] = *(const unsigned*)&Xs[(m0 + g) * 136 + k0 + t * 2];
            a[1] = *(const unsigned*)&Xs[(m0 + g + 8) * 136 + k0 + t * 2];
            a[2] = *(const unsigned*)&Xs[(m0 + g) * 136 + k0 + t * 2 + 8];
            a[3] = *(const unsigned*)&Xs[(m0 + g + 8) * 136 + k0 + t * 2 + 8];
            #pragma unroll
            for (int j = 0; j < 8; j++) {
                unsigned bf[2];
                bf[0] = *(const unsigned*)&w1s[(j * 8 + g) * 136 + k0 + t * 2];
                bf[1] = *(const unsigned*)&w1s[(j * 8 + g) * 136 + k0 + t * 2 + 8];
                mma_m16n8k16(y[j], a, bf);
            }
        }
        #pragma unroll
        for (int j = 0; j < 8; j++) {
            int colg = jc * 64 + j * 8 + t * 2;
            float bb0 = __ldg(&b1g[colg]);
            float bb1 = __ldg(&b1g[colg + 1]);
            float v0 = fmaxf(y[j][0] + bb0, 0.f);
            float v1 = fmaxf(y[j][1] + bb1, 0.f);
            float v2 = fmaxf(y[j][2] + bb0, 0.f);
            float v3 = fmaxf(y[j][3] + bb1, 0.f);
            *(__half2*)&Rs[(m0 + g) * 72 + j * 8 + t * 2]     = __floats2half2_rn(v0, v1);
            *(__half2*)&Rs[(m0 + g + 8) * 72 + j * 8 + t * 2] = __floats2half2_rn(v2, v3);
        }
        __syncthreads();

        #pragma unroll
        for (int k0 = 0; k0 < 64; k0 += 16) {
            unsigned aA[4], aB[4];
            aA[0] = *(const unsigned*)&Rs[(ma + g) * 72 + k0 + t * 2];
            aA[1] = *(const unsigned*)&Rs[(ma + g + 8) * 72 + k0 + t * 2];
            aA[2] = *(const unsigned*)&Rs[(ma + g) * 72 + k0 + t * 2 + 8];
            aA[3] = *(const unsigned*)&Rs[(ma + g + 8) * 72 + k0 + t * 2 + 8];
            aB[0] = *(const unsigned*)&Rs[(ma + 16 + g) * 72 + k0 + t * 2];
            aB[1] = *(const unsigned*)&Rs[(ma + 24 + g) * 72 + k0 + t * 2];
            aB[2] = *(const unsigned*)&Rs[(ma + 16 + g) * 72 + k0 + t * 2 + 8];
            aB[3] = *(const unsigned*)&Rs[(ma + 24 + g) * 72 + k0 + t * 2 + 8];
            #pragma unroll
            for (int j = 0; j < 8; j++) {
                unsigned bf[2];
                bf[0] = *(const unsigned*)&w2s[(nb + j * 8 + g) * 72 + k0 + t * 2];
                bf[1] = *(const unsigned*)&w2s[(nb + j * 8 + g) * 72 + k0 + t * 2 + 8];
                mma_m16n8k16(fc[0][j], aA, bf);
                mma_m16n8k16(fc[1][j], aB, bf);
            }
        }
    }

    #pragma unroll
    for (int i2 = 0; i2 < 2; i2++) {
        #pragma unroll
        for (int j = 0; j < 8; j++) {
            int rl  = ma + i2 * 16 + g;
            int col = nb + j * 8 + t * 2;
            float b20 = __ldg(&b2g[col]);
            float b21 = __ldg(&b2g[col + 1]);
            int r0 = rows_base + rl;
            if (r0 < NN) {
                float2 o;
                o.x = fc[i2][j][0] + b20 + rsts[rl * 132 + col];
                o.y = fc[i2][j][1] + b21 + rsts[rl * 132 + col + 1];
                *(float2*)&out[(size_t)r0 * 128 + col] = o;
            }
            int r8 = r0 + 8;
            if (r8 < NN) {
                float2 o;
                o.x = fc[i2][j][2] + b20 + rsts[(rl + 8) * 132 + col];
                o.y = fc[i2][j][3] + b21 + rsts[(rl + 8) * 132 + col + 1];
                *(float2*)&out[(size_t)r8 * 128 + col] = o;
            }
        }
    }
}

extern "C" void kernel_launch(void* const* d_in, const int* in_sizes, int n_in,
                              void* d_out, int out_size) {
    const float* ent    = (const float*)d_in[0];
    const int*   src    = (const int*)d_in[1];
    const int*   dst    = (const int*)d_in[2];
    const float* W_ent  = (const float*)d_in[3];
    const float* attn_h = (const float*)d_in[4];
    const float* attn_t = (const float*)d_in[5];
    const float* ln1_g  = (const float*)d_in[6];
    const float* ln1_b  = (const float*)d_in[7];
    const float* ln2_g  = (const float*)d_in[8];
    const float* ln2_b  = (const float*)d_in[9];
    const float* w1     = (const float*)d_in[10];
    const float* b1     = (const float*)d_in[11];
    const float* w2     = (const float*)d_in[12];
    const float* b2     = (const float*)d_in[13];
    float* out = (float*)d_out;

    cudaFuncSetAttribute(k_ffn, cudaFuncAttributeMaxDynamicSharedMemorySize, FFN_SMEM);
    cudaFuncSetAttribute(k1, cudaFuncAttributeMaxDynamicSharedMemorySize, K1_SMEM);

    k_zero<<<(NN + 255) / 256, 256>>>();
    k1<<<(NN + 127) / 128, 256, K1_SMEM>>>(ent, W_ent, attn_h, attn_t, ln1_g, ln1_b);
    k_hist<<<EE / 256, 256>>>(dst);
    k_scan1<<<SCAN_NB, 256>>>();
    k_scan2<<<1, 512>>>();
    k_scan3<<<SCAN_NB, 256>>>();
    k_scatter<<<EE / 256, 256>>>(src, dst);
    k_softmax<<<NN / 8, 256>>>();
    for (int hop = 0; hop < 6; hop++) {
        k_hop<<<NN / 8, 256>>>(hop);
    }
    k_ffn<<<(NN + 127) / 128, 256, FFN_SMEM>>>(out, ln2_g, ln2_b, w1, b1, w2, b2);
}

// round 5
// speedup vs baseline: 1.3823x; 1.0795x over previous
#include <cuda_runtime.h>
#include <cuda_fp16.h>

#define NN 100000
#define EE 1600000
#define DD 128
#define HH 8

// ---------------- scratch (static device globals; no allocations) ----------------
__device__ float  g_h[NN * DD];        // LN1 output (fp32, needed for rst)
__device__ float  g_feat0[NN * DD];    // h @ W^T (fp32 anchor for ALPHA term)
__device__ __half g_f0h[NN * DD];      // fp16 copy of feat0 (hop-0 gather input)
__device__ __half g_hA[NN * DD];       // ping
__device__ __half g_hB[NN * DD];       // pong (final hop output)
__device__ float  g_eh[NN * HH];
__device__ float  g_et[NN * HH];
__device__ int    g_count[NN];
__device__ int    g_cursor[NN];
__device__ int    g_rowptr[NN + 1];
__device__ int    g_srcs[EE];          // src per CSR-sorted edge
__device__ __half g_ah[EE * HH];       // normalized attention (fp16)
__device__ int    g_bsum[512];
__device__ int    g_boff[512];
__device__ __half g_w1h[512 * 128];    // fp16 weights (precomputed once)
__device__ __half g_w2h[128 * 512];

#define SCAN_NB 391  // ceil(NN/256)

// ---------------- weight fp16 precompute ----------------
__global__ void k_cvtw(const float* __restrict__ w1, const float* __restrict__ w2) {
    int i = blockIdx.x * 256 + threadIdx.x;
    if (i < 512 * 128) {
        g_w1h[i] = __float2half_rn(w1[i]);
        g_w2h[i] = __float2half_rn(w2[i]);
    }
}

// ---------------- CSR build ----------------
__global__ void k_zero() {
    int i = blockIdx.x * 256 + threadIdx.x;
    if (i < NN) { g_count[i] = 0; g_cursor[i] = 0; }
}

__global__ void k_hist(const int* __restrict__ dst) {
    int e = blockIdx.x * 256 + threadIdx.x;
    if (e < EE) atomicAdd(&g_count[dst[e]], 1);
}

// pass 1: per-block inclusive scan -> rowptr[i+1], block totals -> g_bsum
__global__ __launch_bounds__(256) void k_scan1() {
    __shared__ int ws[8];
    int t = threadIdx.x, lane = t & 31, wid = t >> 5;
    int i = blockIdx.x * 256 + t;
    int v = (i < NN) ? g_count[i] : 0;
    int x = v;
    #pragma unroll
    for (int d = 1; d < 32; d <<= 1) {
        int y = __shfl_up_sync(0xffffffffu, x, d);
        if (lane >= d) x += y;
    }
    if (lane == 31) ws[wid] = x;
    __syncthreads();
    if (wid == 0) {
        int w = (lane < 8) ? ws[lane] : 0;
        #pragma unroll
        for (int d = 1; d < 8; d <<= 1) {
            int y = __shfl_up_sync(0xffffffffu, w, d);
            if (lane >= d) w += y;
        }
        if (lane < 8) ws[lane] = w;
    }
    __syncthreads();
    x += (wid ? ws[wid - 1] : 0);
    if (i < NN) g_rowptr[i + 1] = x;
    if (t == 255) g_bsum[blockIdx.x] = x;
}

// pass 2: exclusive scan of 391 block totals (single block, 512 threads)
__global__ __launch_bounds__(512) void k_scan2() {
    __shared__ int ws[16];
    int t = threadIdx.x, lane = t & 31, wid = t >> 5;
    int v = (t < SCAN_NB) ? g_bsum[t] : 0;
    int x = v;
    #pragma unroll
    for (int d = 1; d < 32; d <<= 1) {
        int y = __shfl_up_sync(0xffffffffu, x, d);
        if (lane >= d) x += y;
    }
    if (lane == 31) ws[wid] = x;
    __syncthreads();
    if (wid == 0) {
        int w = (lane < 16) ? ws[lane] : 0;
        #pragma unroll
        for (int d = 1; d < 16; d <<= 1) {
            int y = __shfl_up_sync(0xffffffffu, w, d);
            if (lane >= d) w += y;
        }
        if (lane < 16) ws[lane] = w;
    }
    __syncthreads();
    x += (wid ? ws[wid - 1] : 0);
    if (t < SCAN_NB) g_boff[t] = x - v;
}

// pass 3: add block offsets
__global__ void k_scan3() {
    int i = blockIdx.x * 256 + threadIdx.x;
    if (i < NN) g_rowptr[i + 1] += g_boff[i >> 8];
    if (i == 0) g_rowptr[0] = 0;
}

__global__ void k_scatter(const int* __restrict__ src, const int* __restrict__ dst) {
    int e = blockIdx.x * 256 + threadIdx.x;
    if (e < EE) {
        int d = dst[e];
        int pos = g_rowptr[d] + atomicAdd(&g_cursor[d], 1);
        g_srcs[pos] = src[e];
    }
}

// ---------------- mma helper ----------------
__device__ __forceinline__ void mma_m16n8k16(float* c, const unsigned* a, const unsigned* b) {
    asm volatile(
        "mma.sync.aligned.m16n8k16.row.col.f32.f16.f16.f32 "
        "{%0,%1,%2,%3}, {%4,%5,%6,%7}, {%8,%9}, {%0,%1,%2,%3};\n"
        : "+f"(c[0]), "+f"(c[1]), "+f"(c[2]), "+f"(c[3])
        : "r"(a[0]), "r"(a[1]), "r"(a[2]), "r"(a[3]), "r"(b[0]), "r"(b[1]));
}

// ---------------- k1: LN1 + h@W^T (tensor core) + attention dots ----------------
// smem layout: sh_ah[128]f | sh_at[128]f | (Ws[128][136]h | Xs[128][136]h)  U  fs[128][132]f
#define K1_AH   0
#define K1_AT   512
#define K1_WS   1024
#define K1_XS   (1024 + 34816)
#define K1_FS   1024
#define K1_SMEM (1024 + 34816 + 34816)

__global__ __launch_bounds__(256) void k1(const float* __restrict__ ent,
                                          const float* __restrict__ W,
                                          const float* __restrict__ ah,
                                          const float* __restrict__ at,
                                          const float* __restrict__ g1v,
                                          const float* __restrict__ b1v) {
    extern __shared__ char sm[];
    float*  sh_ah = (float*)(sm + K1_AH);
    float*  sh_at = (float*)(sm + K1_AT);
    __half* Ws    = (__half*)(sm + K1_WS);
    __half* Xs    = (__half*)(sm + K1_XS);
    float*  fs    = (float*)(sm + K1_FS);

    int tid = threadIdx.x, lane = tid & 31, wid = tid >> 5;
    int g = lane >> 2, t = lane & 3;
    int rows_base = blockIdx.x * 128;

    for (int i = tid; i < 128 * 128; i += 256) {
        Ws[(i >> 7) * 136 + (i & 127)] = __float2half_rn(W[i]);
    }
    for (int i = tid; i < 128; i += 256) { sh_ah[i] = ah[i]; sh_at[i] = at[i]; }

    float4 gg = ((const float4*)g1v)[lane];
    float4 bb = ((const float4*)b1v)[lane];

    // LN1 prologue: warp owns 16 rows
    for (int i = 0; i < 16; i++) {
        int rl = wid * 16 + i;
        int r = rows_base + rl;
        int rc = (r < NN) ? r : (NN - 1);
        float4 x = __ldg(&((const float4*)ent)[rc * 32 + lane]);
        float s  = x.x + x.y + x.z + x.w;
        float sq = x.x * x.x + x.y * x.y + x.z * x.z + x.w * x.w;
        #pragma unroll
        for (int d = 16; d; d >>= 1) {
            s  += __shfl_xor_sync(0xffffffffu, s, d);
            sq += __shfl_xor_sync(0xffffffffu, sq, d);
        }
        float mean = s * 0.0078125f;
        float var  = sq * 0.0078125f - mean * mean;
        float rstd = rsqrtf(var + 1e-5f);
        float4 hv;
        hv.x = (x.x - mean) * rstd * gg.x + bb.x;
        hv.y = (x.y - mean) * rstd * gg.y + bb.y;
        hv.z = (x.z - mean) * rstd * gg.z + bb.z;
        hv.w = (x.w - mean) * rstd * gg.w + bb.w;
        if (r < NN) ((float4*)g_h)[r * 32 + lane] = hv;
        __half2* xp = (__half2*)&Xs[rl * 136 + lane * 4];
        xp[0] = __floats2half2_rn(hv.x, hv.y);
        xp[1] = __floats2half2_rn(hv.z, hv.w);
    }
    __syncthreads();

    // GEMM: warp computes rows [wid*16, +16) x all 128 cols
    float y[16][4];
    #pragma unroll
    for (int j = 0; j < 16; j++)
        #pragma unroll
        for (int c = 0; c < 4; c++) y[j][c] = 0.f;
    int m0 = wid * 16;
    #pragma unroll
    for (int k0 = 0; k0 < 128; k0 += 16) {
        unsigned a[4];
        a[0] = *(const unsigned*)&Xs[(m0 + g) * 136 + k0 + t * 2];
        a[1] = *(const unsigned*)&Xs[(m0 + g + 8) * 136 + k0 + t * 2];
        a[2] = *(const unsigned*)&Xs[(m0 + g) * 136 + k0 + t * 2 + 8];
        a[3] = *(const unsigned*)&Xs[(m0 + g + 8) * 136 + k0 + t * 2 + 8];
        #pragma unroll
        for (int j = 0; j < 16; j++) {
            unsigned bf[2];
            bf[0] = *(const unsigned*)&Ws[(j * 8 + g) * 136 + k0 + t * 2];
            bf[1] = *(const unsigned*)&Ws[(j * 8 + g) * 136 + k0 + t * 2 + 8];
            mma_m16n8k16(y[j], a, bf);
        }
    }
    __syncthreads();   // Ws/Xs dead; fs aliases them

    // store feat (fp32 + fp16 global) and fs (smem for dots)
    #pragma unroll
    for (int j = 0; j < 16; j++) {
        int col = j * 8 + t * 2;
        int rl0 = m0 + g;
        fs[rl0 * 132 + col]       = y[j][0];
        fs[rl0 * 132 + col + 1]   = y[j][1];
        fs[(rl0 + 8) * 132 + col]     = y[j][2];
        fs[(rl0 + 8) * 132 + col + 1] = y[j][3];
        int r0 = rows_base + rl0;
        if (r0 < NN) {
            *(float2*)&g_feat0[(size_t)r0 * 128 + col] = make_float2(y[j][0], y[j][1]);
            *(__half2*)&g_f0h[(size_t)r0 * 128 + col]  = __floats2half2_rn(y[j][0], y[j][1]);
        }
        if (r0 + 8 < NN) {
            *(float2*)&g_feat0[(size_t)(r0 + 8) * 128 + col] = make_float2(y[j][2], y[j][3]);
            *(__half2*)&g_f0h[(size_t)(r0 + 8) * 128 + col]  = __floats2half2_rn(y[j][2], y[j][3]);
        }
    }
    __syncthreads();

    // attention dots: lane covers 4 consecutive dims of head hh2
    int hh2 = lane >> 2;
    int d0 = (lane & 3) * 4;
    float a0 = sh_ah[hh2 * 16 + d0 + 0], a1 = sh_ah[hh2 * 16 + d0 + 1];
    float a2 = sh_ah[hh2 * 16 + d0 + 2], a3 = sh_ah[hh2 * 16 + d0 + 3];
    float t0 = sh_at[hh2 * 16 + d0 + 0], t1 = sh_at[hh2 * 16 + d0 + 1];
    float t2 = sh_at[hh2 * 16 + d0 + 2], t3 = sh_at[hh2 * 16 + d0 + 3];
    for (int i = 0; i < 16; i++) {
        int rl = wid * 16 + i;
        int r = rows_base + rl;
        float4 f = *(const float4*)&fs[rl * 132 + lane * 4];
        float pe = f.x * a0 + f.y * a1 + f.z * a2 + f.w * a3;
        float pt = f.x * t0 + f.y * t1 + f.z * t2 + f.w * t3;
        pe += __shfl_xor_sync(0xffffffffu, pe, 1);
        pe += __shfl_xor_sync(0xffffffffu, pe, 2);
        pt += __shfl_xor_sync(0xffffffffu, pt, 1);
        pt += __shfl_xor_sync(0xffffffffu, pt, 2);
        if ((lane & 3) == 0 && r < NN) {
            g_eh[r * 8 + hh2] = pe;
            g_et[r * 8 + hh2] = pt;
        }
    }
}

// ---------------- segment softmax: 3 passes, exp recompute, fp16 store ----------------
__global__ __launch_bounds__(256) void k_softmax() {
    int v = blockIdx.x * 8 + (threadIdx.x >> 5);
    int lane = threadIdx.x & 31;
    if (v >= NN) return;
    int beg = g_rowptr[v], end = g_rowptr[v + 1];
    int head = lane & 7, eo = lane >> 3;
    float etv = g_et[v * 8 + head];

    float m = -1e30f;
    for (int e = beg + eo; e < end; e += 4) {
        int s = __ldg(&g_srcs[e]);
        float sc = __ldg(&g_eh[s * 8 + head]) + etv;
        sc = sc > 0.f ? sc : 0.2f * sc;
        m = fmaxf(m, sc);
    }
    m = fmaxf(m, __shfl_xor_sync(0xffffffffu, m, 8));
    m = fmaxf(m, __shfl_xor_sync(0xffffffffu, m, 16));

    float ssum = 0.f;
    for (int e = beg + eo; e < end; e += 4) {
        int s = __ldg(&g_srcs[e]);
        float sc = __ldg(&g_eh[s * 8 + head]) + etv;
        sc = sc > 0.f ? sc : 0.2f * sc;
        ssum += __expf(sc - m);
    }
    ssum += __shfl_xor_sync(0xffffffffu, ssum, 8);
    ssum += __shfl_xor_sync(0xffffffffu, ssum, 16);
    float inv = 1.f / ssum;

    for (int e = beg + eo; e < end; e += 4) {
        int s = __ldg(&g_srcs[e]);
        float sc = __ldg(&g_eh[s * 8 + head]) + etv;
        sc = sc > 0.f ? sc : 0.2f * sc;
        g_ah[e * 8 + head] = __float2half_rn(__expf(sc - m) * inv);
    }
}

// ---------------- propagation hop: half-warp per edge, 2 edges/iter ----------------
__global__ __launch_bounds__(256) void k_hop(int which) {
    const __half* fin  = (which == 0) ? g_f0h : ((which & 1) ? g_hA : g_hB);
    __half*       fout = (which & 1) ? g_hB : g_hA;
    int v = blockIdx.x * 8 + (threadIdx.x >> 5);
    int lane = threadIdx.x & 31;
    if (v >= NN) return;
    int beg = g_rowptr[v], end = g_rowptr[v + 1];
    int half = lane >> 4;      // which edge of the pair
    int sl   = lane & 15;      // sub-lane: owns dims [sl*8, sl*8+8)
    int hh   = sl >> 1;        // head for those dims
    float acc[8] = {0.f, 0.f, 0.f, 0.f, 0.f, 0.f, 0.f, 0.f};

    for (int e0 = beg; e0 < end; e0 += 2) {
        int e = e0 + half;
        bool valid = (e < end);
        int ec = valid ? e : (end - 1);
        int s = __ldg(&g_srcs[ec]);
        float av = valid ? __half2float(__ldg(&g_ah[ec * 8 + hh])) : 0.f;
        uint4 p = __ldg((const uint4*)(fin + (size_t)s * 128 + sl * 8));
        __half2* hp = (__half2*)&p;
        #pragma unroll
        for (int q = 0; q < 4; q++) {
            float2 f = __half22float2(hp[q]);
            acc[2 * q]     += av * f.x;
            acc[2 * q + 1] += av * f.y;
        }
    }
    #pragma unroll
    for (int q = 0; q < 8; q++)
        acc[q] += __shfl_xor_sync(0xffffffffu, acc[q], 16);

    if (half == 0) {
        const float* f0p = g_feat0 + (size_t)v * 128 + sl * 8;
        float4 fa = __ldg((const float4*)f0p);
        float4 fb = __ldg((const float4*)(f0p + 4));
        __half2 o0 = __floats2half2_rn(0.85f * acc[0] + 0.15f * fa.x,
                                       0.85f * acc[1] + 0.15f * fa.y);
        __half2 o1 = __floats2half2_rn(0.85f * acc[2] + 0.15f * fa.z,
                                       0.85f * acc[3] + 0.15f * fa.w);
        __half2 o2 = __floats2half2_rn(0.85f * acc[4] + 0.15f * fb.x,
                                       0.85f * acc[5] + 0.15f * fb.y);
        __half2 o3 = __floats2half2_rn(0.85f * acc[6] + 0.15f * fb.z,
                                       0.85f * acc[7] + 0.15f * fb.w);
        uint4 val;
        val.x = *(unsigned*)&o0;
        val.y = *(unsigned*)&o1;
        val.z = *(unsigned*)&o2;
        val.w = *(unsigned*)&o3;
        *(uint4*)(fout + (size_t)v * 128 + sl * 8) = val;
    }
}

// ---------------- FFN: rst = hB + h; LN2; relu(x@w1^T+b1)@w2^T+b2 + rst ----------------
#define XS_OFF   0
#define W1S_OFF  (34816)
#define RS_OFF   (34816 + 17408)
#define W2S_OFF  (34816 + 17408 + 18432)
#define RST_OFF  (34816 + 17408 + 18432 + 18432)
#define FFN_SMEM (34816 + 17408 + 18432 + 18432 + 67584)

__global__ __launch_bounds__(256) void k_ffn(float* __restrict__ out,
                                             const float* __restrict__ g2,
                                             const float* __restrict__ b2v,
                                             const float* __restrict__ b1g,
                                             const float* __restrict__ b2g) {
    extern __shared__ char smem[];
    __half* Xs   = (__half*)(smem + XS_OFF);    // [128][136]
    __half* w1s  = (__half*)(smem + W1S_OFF);   // [64][136]
    __half* Rs   = (__half*)(smem + RS_OFF);    // [128][72]
    __half* w2s  = (__half*)(smem + W2S_OFF);   // [128][72]
    float*  rsts = (float*)(smem + RST_OFF);    // [128][132]

    int tid = threadIdx.x, lane = tid & 31, wid = tid >> 5;
    int g = lane >> 2, t = lane & 3;
    int rows_base = blockIdx.x * 128;

    float4 gg = ((const float4*)g2)[lane];
    float4 bb = ((const float4*)b2v)[lane];

    // prologue: rst + LN2 + fp16 X
    for (int i = 0; i < 16; i++) {
        int rl = wid * 16 + i;
        int r = rows_base + rl;
        if (r >= NN) r = NN - 1;
        uint2 p = __ldg(((const uint2*)(g_hB + (size_t)r * 128)) + lane);
        __half2 h0 = *(__half2*)&p.x;
        __half2 h1 = *(__half2*)&p.y;
        float2 f0 = __half22float2(h0);
        float2 f1 = __half22float2(h1);
        float4 hv = __ldg(&((const float4*)g_h)[(size_t)r * 32 + lane]);
        float4 rv;
        rv.x = f0.x + hv.x; rv.y = f0.y + hv.y; rv.z = f1.x + hv.z; rv.w = f1.y + hv.w;
        *(float4*)&rsts[rl * 132 + lane * 4] = rv;
        float s  = rv.x + rv.y + rv.z + rv.w;
        float sq = rv.x * rv.x + rv.y * rv.y + rv.z * rv.z + rv.w * rv.w;
        #pragma unroll
        for (int d = 16; d; d >>= 1) {
            s  += __shfl_xor_sync(0xffffffffu, s, d);
            sq += __shfl_xor_sync(0xffffffffu, sq, d);
        }
        float mean = s * 0.0078125f;
        float var  = sq * 0.0078125f - mean * mean;
        float rstd = rsqrtf(var + 1e-5f);
        float4 xv;
        xv.x = (rv.x - mean) * rstd * gg.x + bb.x;
        xv.y = (rv.y - mean) * rstd * gg.y + bb.y;
        xv.z = (rv.z - mean) * rstd * gg.z + bb.z;
        xv.w = (rv.w - mean) * rstd * gg.w + bb.w;
        __half2* xp = (__half2*)&Xs[rl * 136 + lane * 4];
        xp[0] = __floats2half2_rn(xv.x, xv.y);
        xp[1] = __floats2half2_rn(xv.z, xv.w);
    }

    float fc[2][8][4];
    #pragma unroll
    for (int i2 = 0; i2 < 2; i2++)
        #pragma unroll
        for (int j = 0; j < 8; j++)
            #pragma unroll
            for (int c = 0; c < 4; c++) fc[i2][j][c] = 0.f;

    int wm = wid >> 1, wn = wid & 1;
    int ma = wm * 32, nb = wn * 64;

    for (int jc = 0; jc < 8; jc++) {
        __syncthreads();
        // load current w1/w2 fp16 chunks (vectorized smem copies)
        for (int i = tid; i < 64 * 16; i += 256) {        // 1024 uint4
            int rr = i >> 4, c8 = i & 15;
            *(uint4*)&w1s[rr * 136 + c8 * 8] =
                *(const uint4*)&g_w1h[(jc * 64 + rr) * 128 + c8 * 8];
        }
        for (int i = tid; i < 128 * 8; i += 256) {        // 1024 uint4
            int rr = i >> 3, c8 = i & 7;
            *(uint4*)&w2s[rr * 72 + c8 * 8] =
                *(const uint4*)&g_w2h[rr * 512 + jc * 64 + c8 * 8];
        }
        __syncthreads();

        float y[8][4];
        #pragma unroll
        for (int j = 0; j < 8; j++)
            #pragma unroll
            for (int c = 0; c < 4; c++) y[j][c] = 0.f;
        int m0 = wid * 16;
        #pragma unroll
        for (int k0 = 0; k0 < 128; k0 += 16) {
            unsigned a[4];
            a[0] = *(const unsigned*)&Xs[(m0 + g) * 136 + k0 + t * 2];
            a[1] = *(const unsigned*)&Xs[(m0 + g + 8) * 136 + k0 + t * 2];
            a[2] = *(const unsigned*)&Xs[(m0 + g) * 136 + k0 + t * 2 + 8];
            a[3] = *(const unsigned*)&Xs[(m0 + g + 8) * 136 + k0 + t * 2 + 8];
            #pragma unroll
            for (int j = 0; j < 8; j++) {
                unsigned bf[2];
                bf[0] = *(const unsigned*)&w1s[(j * 8 + g) * 136 + k0 + t * 2];
                bf[1] = *(const unsigned*)&w1s[(j * 8 + g) * 136 + k0 + t * 2 + 8];
                mma_m16n8k16(y[j], a, bf);
            }
        }
        #pragma unroll
        for (int j = 0; j < 8; j++) {
            int colg = jc * 64 + j * 8 + t * 2;
            float bb0 = __ldg(&b1g[colg]);
            float bb1 = __ldg(&b1g[colg + 1]);
            float v0 = fmaxf(y[j][0] + bb0, 0.f);
            float v1 = fmaxf(y[j][1] + bb1, 0.f);
            float v2 = fmaxf(y[j][2] + bb0, 0.f);
            float v3 = fmaxf(y[j][3] + bb1, 0.f);
            *(__half2*)&Rs[(m0 + g) * 72 + j * 8 + t * 2]     = __floats2half2_rn(v0, v1);
            *(__half2*)&Rs[(m0 + g + 8) * 72 + j * 8 + t * 2] = __floats2half2_rn(v2, v3);
        }
        __syncthreads();

        #pragma unroll
        for (int k0 = 0; k0 < 64; k0 += 16) {
            unsigned aA[4], aB[4];
            aA[0] = *(const unsigned*)&Rs[(ma + g) * 72 + k0 + t * 2];
            aA[1] = *(const unsigned*)&Rs[(ma + g + 8) * 72 + k0 + t * 2];
            aA[2] = *(const unsigned*)&Rs[(ma + g) * 72 + k0 + t * 2 + 8];
            aA[3] = *(const unsigned*)&Rs[(ma + g + 8) * 72 + k0 + t * 2 + 8];
            aB[0] = *(const unsigned*)&Rs[(ma + 16 + g) * 72 + k0 + t * 2];
            aB[1] = *(const unsigned*)&Rs[(ma + 24 + g) * 72 + k0 + t * 2];
            aB[2] = *(const unsigned*)&Rs[(ma + 16 + g) * 72 + k0 + t * 2 + 8];
            aB[3] = *(const unsigned*)&Rs[(ma + 24 + g) * 72 + k0 + t * 2 + 8];
            #pragma unroll
            for (int j = 0; j < 8; j++) {
                unsigned bf[2];
                bf[0] = *(const unsigned*)&w2s[(nb + j * 8 + g) * 72 + k0 + t * 2];
                bf[1] = *(const unsigned*)&w2s[(nb + j * 8 + g) * 72 + k0 + t * 2 + 8];
                mma_m16n8k16(fc[0][j], aA, bf);
                mma_m16n8k16(fc[1][j], aB, bf);
            }
        }
    }

    #pragma unroll
    for (int i2 = 0; i2 < 2; i2++) {
        #pragma unroll
        for (int j = 0; j < 8; j++) {
            int rl  = ma + i2 * 16 + g;
            int col = nb + j * 8 + t * 2;
            float b20 = __ldg(&b2g[col]);
            float b21 = __ldg(&b2g[col + 1]);
            int r0 = rows_base + rl;
            if (r0 < NN) {
                float2 o;
                o.x = fc[i2][j][0] + b20 + rsts[rl * 132 + col];
                o.y = fc[i2][j][1] + b21 + rsts[rl * 132 + col + 1];
                *(float2*)&out[(size_t)r0 * 128 + col] = o;
            }
            int r8 = r0 + 8;
            if (r8 < NN) {
                float2 o;
                o.x = fc[i2][j][2] + b20 + rsts[(rl + 8) * 132 + col];
                o.y = fc[i2][j][3] + b21 + rsts[(rl + 8) * 132 + col + 1];
                *(float2*)&out[(size_t)r8 * 128 + col] = o;
            }
        }
    }
}

extern "C" void kernel_launch(void* const* d_in, const int* in_sizes, int n_in,
                              void* d_out, int out_size) {
    const float* ent    = (const float*)d_in[0];
    const int*   src    = (const int*)d_in[1];
    const int*   dst    = (const int*)d_in[2];
    const float* W_ent  = (const float*)d_in[3];
    const float* attn_h = (const float*)d_in[4];
    const float* attn_t = (const float*)d_in[5];
    const float* ln1_g  = (const float*)d_in[6];
    const float* ln1_b  = (const float*)d_in[7];
    const float* ln2_g  = (const float*)d_in[8];
    const float* ln2_b  = (const float*)d_in[9];
    const float* w1     = (const float*)d_in[10];
    const float* b1     = (const float*)d_in[11];
    const float* w2     = (const float*)d_in[12];
    const float* b2     = (const float*)d_in[13];
    float* out = (float*)d_out;

    cudaFuncSetAttribute(k_ffn, cudaFuncAttributeMaxDynamicSharedMemorySize, FFN_SMEM);
    cudaFuncSetAttribute(k1, cudaFuncAttributeMaxDynamicSharedMemorySize, K1_SMEM);

    k_cvtw<<<(512 * 128 + 255) / 256, 256>>>(w1, w2);
    k_zero<<<(NN + 255) / 256, 256>>>();
    k1<<<(NN + 127) / 128, 256, K1_SMEM>>>(ent, W_ent, attn_h, attn_t, ln1_g, ln1_b);
    k_hist<<<EE / 256, 256>>>(dst);
    k_scan1<<<SCAN_NB, 256>>>();
    k_scan2<<<1, 512>>>();
    k_scan3<<<SCAN_NB, 256>>>();
    k_scatter<<<EE / 256, 256>>>(src, dst);
    k_softmax<<<NN / 8, 256>>>();
    for (int hop = 0; hop < 6; hop++) {
        k_hop<<<NN / 8, 256>>>(hop);
    }
    k_ffn<<<(NN + 127) / 128, 256, FFN_SMEM>>>(out, ln2_g, ln2_b, b1, b2);
}